// round 10
// baseline (speedup 1.0000x reference)
#include <cuda_runtime.h>
#include <cuda_fp16.h>
#include <cstdint>

#define N_EDGES   50000
#define N_NODESC  100000
#define TILES     ((N_EDGES + 127) / 128)     // 391
#define ROWS_PAD  (TILES * 128)               // 50048

// ---------------- device scratch (allocation-free) ----------------
__device__ float  g_s;
__device__ uint2  g_xh[N_NODESC * 32];        // x as fp16 [100000,128]
__device__ uint2  g_eph[ROWS_PAD * 32];       // edge_pre as fp16 [50048,128]
__device__ uint2  g_e1h[N_EDGES * 32];        // e1 as fp16 [50000,128]

// ---------------- helpers ----------------
__device__ __forceinline__ void mma16(float* c, const uint32_t* a,
                                      uint32_t b0, uint32_t b1) {
    asm volatile(
        "mma.sync.aligned.m16n8k16.row.col.f32.f16.f16.f32 "
        "{%0,%1,%2,%3},{%4,%5,%6,%7},{%8,%9},{%0,%1,%2,%3};"
        : "+f"(c[0]), "+f"(c[1]), "+f"(c[2]), "+f"(c[3])
        : "r"(a[0]), "r"(a[1]), "r"(a[2]), "r"(a[3]), "r"(b0), "r"(b1));
}

// ---------------------------------------------------------------------------
// inter_nw = mean_i cos(w3[i], w3[0])
// ---------------------------------------------------------------------------
__global__ void k_internw(const float* __restrict__ w3) {
    __shared__ float sdot[128], snrm[128], red[4];
    int t = threadIdx.x, w = t >> 5, lane = t & 31;   // 512 threads
    for (int row = w; row < 128; row += 16) {
        float d = 0.f, n = 0.f;
#pragma unroll
        for (int jj = 0; jj < 4; jj++) {
            int j = jj * 32 + lane;
            float v = w3[row * 128 + j];
            d += v * w3[j];
            n += v * v;
        }
#pragma unroll
        for (int o = 16; o; o >>= 1) {
            d += __shfl_xor_sync(0xffffffffu, d, o);
            n += __shfl_xor_sync(0xffffffffu, n, o);
        }
        if (lane == 0) { sdot[row] = d; snrm[row] = n; }
    }
    __syncthreads();
    if (t < 128) {
        float c = sdot[t] / (sqrtf(snrm[0]) * sqrtf(snrm[t]));
#pragma unroll
        for (int o = 16; o; o >>= 1) c += __shfl_xor_sync(0xffffffffu, c, o);
        if (lane == 0) red[t >> 5] = c;
    }
    __syncthreads();
    if (t == 0) g_s = (red[0] + red[1] + red[2] + red[3]) * (1.0f / 128.0f);
}

// ---------------------------------------------------------------------------
// fp32 -> fp16 table convert (x)
// ---------------------------------------------------------------------------
__global__ void k_tohalf(const float4* __restrict__ src,
                         uint2* __restrict__ dst, int n4) {
    int i = blockIdx.x * blockDim.x + threadIdx.x;
    if (i >= n4) return;
    float4 v = src[i];
    __half2 a = __floats2half2_rn(v.x, v.y);
    __half2 b = __floats2half2_rn(v.z, v.w);
    dst[i] = make_uint2(*(uint32_t*)&a, *(uint32_t*)&b);
}

// ---------------------------------------------------------------------------
// Masked-mean gather over fp16 rows. One warp/row; lane owns 4 cols.
// OUTF32: write float4; else write half uint2.
// ---------------------------------------------------------------------------
template <int ARITY, bool OUTF32>
__global__ void k_gather_h(const uint2* __restrict__ src,
                           const int* __restrict__ idxmat,
                           void* __restrict__ dstv, int rows) {
    int w = (blockIdx.x * blockDim.x + threadIdx.x) >> 5;
    int lane = threadIdx.x & 31;
    if (w >= rows) return;

    int idx = 0;
    if (lane < ARITY) idx = idxmat[w * ARITY + lane];
    unsigned on = __ballot_sync(0xffffffffu, (lane < ARITY) && (idx > 0));
    int cnt = __popc(on);
    float wn = cnt ? (1.0f / (float)cnt) : (1.0f / (float)ARITY);

    float4 acc = make_float4(0.f, 0.f, 0.f, 0.f);
#pragma unroll
    for (int a = 0; a < ARITY; a++) {
        int ia = __shfl_sync(0xffffffffu, idx, a);
        float wa = cnt ? (((on >> a) & 1u) ? wn : 0.0f) : wn;
        uint2 u = src[ia * 32 + lane];
        float2 f0 = __half22float2(*(__half2*)&u.x);
        float2 f1 = __half22float2(*(__half2*)&u.y);
        acc.x += wa * f0.x; acc.y += wa * f0.y;
        acc.z += wa * f1.x; acc.w += wa * f1.y;
    }
    if (OUTF32) {
        ((float4*)dstv)[w * 32 + lane] = acc;
    } else {
        __half2 a = __floats2half2_rn(acc.x, acc.y);
        __half2 b = __floats2half2_rn(acc.z, acc.w);
        ((uint2*)dstv)[w * 32 + lane] = make_uint2(*(uint32_t*)&a, *(uint32_t*)&b);
    }
}

// ---------------------------------------------------------------------------
// Fused dual GEMM (fp16 m16n8k16 mma, fp32 accum): e1 = relu(s*A@W1)@W2
// 128 rows/CTA, 512 threads (16 warps), warp tile 32x32, 2 CTAs/SM.
//   sA   [128][136] half  (A, then T1)
//   sW1t [n=128][k=136] half (W1 transposed), sW2t same
// ---------------------------------------------------------------------------
#define PH 136
#define SA_HALFS (128 * PH)
#define SMEM_TOTAL (3 * SA_HALFS * 2)

__device__ __forceinline__ void do_gemm_h(const __half* sA, const __half* sWt,
                                          float acc[2][4][4],
                                          int mrow0, int ncol0,
                                          int g, int tig) {
#pragma unroll
    for (int k0 = 0; k0 < 128; k0 += 16) {
        uint32_t a[2][4];
#pragma unroll
        for (int ms = 0; ms < 2; ms++) {
            const __half* p = sA + (mrow0 + ms * 16 + g) * PH + k0 + 2 * tig;
            a[ms][0] = *(const uint32_t*)(p);
            a[ms][1] = *(const uint32_t*)(p + 8 * PH);
            a[ms][2] = *(const uint32_t*)(p + 8);
            a[ms][3] = *(const uint32_t*)(p + 8 * PH + 8);
        }
#pragma unroll
        for (int ns = 0; ns < 4; ns++) {
            const __half* q = sWt + (ncol0 + ns * 8 + g) * PH + k0 + 2 * tig;
            uint32_t b0 = *(const uint32_t*)(q);
            uint32_t b1 = *(const uint32_t*)(q + 8);
            mma16(acc[0][ns], a[0], b0, b1);
            mma16(acc[1][ns], a[1], b0, b1);
        }
    }
}

__global__ void __launch_bounds__(512)
k_dualgemm(const uint2* __restrict__ Aeph, const float* __restrict__ w1,
           const float* __restrict__ w2, __half2* __restrict__ e1h, int M) {
    extern __shared__ __align__(16) __half smem[];
    __half* sA   = smem;
    __half* sW1t = smem + SA_HALFS;
    __half* sW2t = sW1t + SA_HALFS;

    int t = threadIdx.x;
    int w = t >> 5, lane = t & 31;
    int g = lane >> 2, tig = lane & 3;
    int row0 = blockIdx.x * 128;

    // ---- load weights transposed (Wt[n][k] = W[k][n]) as fp16 ----
    for (int i = t; i < 4096; i += 512) {
        int k = i >> 5, q = (i & 31) * 4;
        float4 v1 = *(const float4*)&w1[k * 128 + q];
        float4 v2 = *(const float4*)&w2[k * 128 + q];
        sW1t[(q + 0) * PH + k] = __float2half_rn(v1.x);
        sW1t[(q + 1) * PH + k] = __float2half_rn(v1.y);
        sW1t[(q + 2) * PH + k] = __float2half_rn(v1.z);
        sW1t[(q + 3) * PH + k] = __float2half_rn(v1.w);
        sW2t[(q + 0) * PH + k] = __float2half_rn(v2.x);
        sW2t[(q + 1) * PH + k] = __float2half_rn(v2.y);
        sW2t[(q + 2) * PH + k] = __float2half_rn(v2.z);
        sW2t[(q + 3) * PH + k] = __float2half_rn(v2.w);
    }
    // ---- load A tile (already fp16), zero tail rows ----
    for (int i = t; i < 4096; i += 512) {
        int r = i >> 5, c8 = i & 31;
        uint2 u = (row0 + r < M) ? Aeph[(size_t)(row0 + r) * 32 + c8]
                                 : make_uint2(0u, 0u);
        *(uint2*)&sA[r * PH + c8 * 4] = u;
    }
    __syncthreads();

    int mrow0 = (w & 3) * 32;       // warp row strip
    int ncol0 = (w >> 2) * 32;      // warp col quarter

    float acc[2][4][4];
#pragma unroll
    for (int ms = 0; ms < 2; ms++)
#pragma unroll
        for (int ns = 0; ns < 4; ns++)
#pragma unroll
            for (int j = 0; j < 4; j++) acc[ms][ns][j] = 0.f;

    // ================= GEMM 1 =================
    do_gemm_h(sA, sW1t, acc, mrow0, ncol0, g, tig);

    float s_nw = g_s;
    __syncthreads();    // all warps done reading sA before overwrite

    // relu(s * acc) -> sA (fp16)
#pragma unroll
    for (int ms = 0; ms < 2; ms++) {
#pragma unroll
        for (int ns = 0; ns < 4; ns++) {
            int r0 = mrow0 + ms * 16 + g;
            int c0 = ncol0 + ns * 8 + 2 * tig;
            __half2 lo = __floats2half2_rn(fmaxf(acc[ms][ns][0] * s_nw, 0.f),
                                           fmaxf(acc[ms][ns][1] * s_nw, 0.f));
            __half2 hi = __floats2half2_rn(fmaxf(acc[ms][ns][2] * s_nw, 0.f),
                                           fmaxf(acc[ms][ns][3] * s_nw, 0.f));
            *(__half2*)&sA[r0 * PH + c0] = lo;
            *(__half2*)&sA[(r0 + 8) * PH + c0] = hi;
#pragma unroll
            for (int j = 0; j < 4; j++) acc[ms][ns][j] = 0.f;
        }
    }
    __syncthreads();

    // ================= GEMM 2 =================
    do_gemm_h(sA, sW2t, acc, mrow0, ncol0, g, tig);

    // write e1 (fp16)
#pragma unroll
    for (int ms = 0; ms < 2; ms++) {
#pragma unroll
        for (int ns = 0; ns < 4; ns++) {
            int r = row0 + mrow0 + ms * 16 + g;
            int c0 = ncol0 + ns * 8 + 2 * tig;     // even
            if (r < M)
                e1h[(size_t)r * 64 + (c0 >> 1)] =
                    __floats2half2_rn(acc[ms][ns][0], acc[ms][ns][1]);
            if (r + 8 < M)
                e1h[(size_t)(r + 8) * 64 + (c0 >> 1)] =
                    __floats2half2_rn(acc[ms][ns][2], acc[ms][ns][3]);
        }
    }
}

// ---------------------------------------------------------------------------
extern "C" void kernel_launch(void* const* d_in, const int* in_sizes, int n_in,
                              void* d_out, int out_size) {
    const float* x    = (const float*)d_in[0];   // [100000,128]
    const int*   seq  = (const int*)d_in[1];     // [50000,32]
    const int*   useq = (const int*)d_in[2];     // [100000,16]
    const float* w1   = (const float*)d_in[4];   // [128,128]
    const float* w2   = (const float*)d_in[5];   // [128,128]
    const float* w3   = (const float*)d_in[6];   // [128,128]
    float* out = (float*)d_out;

    void *p_xh, *p_eph, *p_e1h;
    cudaGetSymbolAddress(&p_xh, g_xh);
    cudaGetSymbolAddress(&p_eph, g_eph);
    cudaGetSymbolAddress(&p_e1h, g_e1h);

    cudaFuncSetAttribute(k_dualgemm,
                         cudaFuncAttributeMaxDynamicSharedMemorySize,
                         SMEM_TOTAL);

    k_internw<<<1, 512>>>(w3);

    // x -> fp16 table
    {
        int n4 = N_NODESC * 32;
        k_tohalf<<<(n4 + 255) / 256, 256>>>((const float4*)x, (uint2*)p_xh, n4);
    }

    // edge_pre[e] = masked-mean_a x_h[seq[e,a]]  (fp32 accum, fp16 out)
    k_gather_h<32, false><<<(N_EDGES + 7) / 8, 256>>>(
        (const uint2*)p_xh, seq, p_eph, N_EDGES);

    // e1 = relu(s * edge_pre @ W1) @ W2   (fp16 mma, fp16 out)
    k_dualgemm<<<TILES, 512, SMEM_TOTAL>>>((const uint2*)p_eph, w1, w2,
                                           (__half2*)p_e1h, N_EDGES);

    // out[n] = masked-mean_k e1_h[useq[n,k]]  (fp32 out)
    k_gather_h<16, true><<<(N_NODESC + 7) / 8, 256>>>(
        (const uint2*)p_e1h, useq, d_out, N_NODESC);
}

// round 13
// speedup vs baseline: 1.8300x; 1.8300x over previous
#include <cuda_runtime.h>
#include <cuda_fp16.h>
#include <cstdint>

#define N_EDGES   50000
#define N_NODESC  100000
#define TILES     ((N_EDGES + 127) / 128)     // 391
#define ROWS_PAD  (TILES * 128)               // 50048

// ---------------- device scratch (allocation-free) ----------------
__device__ float  g_s;
__device__ uint2  g_xh[N_NODESC * 32];        // x as fp16 [100000,128]
__device__ uint2  g_eph[ROWS_PAD * 32];       // edge_pre fp16 [50048,128]
__device__ uint2  g_e1h[N_EDGES * 32];        // e1 fp16 [50000,128]
__device__ uint2  g_w1t[128 * 32];            // W1^T fp16 [n][k]
__device__ uint2  g_w2t[128 * 32];            // W2^T fp16 [n][k]

// ---------------- mma / ldmatrix helpers ----------------
__device__ __forceinline__ void mma16(float* c, const uint32_t* a,
                                      uint32_t b0, uint32_t b1) {
    asm volatile(
        "mma.sync.aligned.m16n8k16.row.col.f32.f16.f16.f32 "
        "{%0,%1,%2,%3},{%4,%5,%6,%7},{%8,%9},{%0,%1,%2,%3};"
        : "+f"(c[0]), "+f"(c[1]), "+f"(c[2]), "+f"(c[3])
        : "r"(a[0]), "r"(a[1]), "r"(a[2]), "r"(a[3]), "r"(b0), "r"(b1));
}
__device__ __forceinline__ void ldsm_x4(uint32_t* r, uint32_t addr) {
    asm volatile(
        "ldmatrix.sync.aligned.m8n8.x4.shared.b16 {%0,%1,%2,%3}, [%4];"
        : "=r"(r[0]), "=r"(r[1]), "=r"(r[2]), "=r"(r[3]) : "r"(addr));
}

// ---------------------------------------------------------------------------
// inter_nw = mean_i cos(w3[i], w3[0])
// ---------------------------------------------------------------------------
__global__ void k_internw(const float* __restrict__ w3) {
    __shared__ float sdot[128], snrm[128], red[4];
    int t = threadIdx.x, w = t >> 5, lane = t & 31;   // 512 threads
    for (int row = w; row < 128; row += 16) {
        float d = 0.f, n = 0.f;
#pragma unroll
        for (int jj = 0; jj < 4; jj++) {
            int j = jj * 32 + lane;
            float v = w3[row * 128 + j];
            d += v * w3[j];
            n += v * v;
        }
#pragma unroll
        for (int o = 16; o; o >>= 1) {
            d += __shfl_xor_sync(0xffffffffu, d, o);
            n += __shfl_xor_sync(0xffffffffu, n, o);
        }
        if (lane == 0) { sdot[row] = d; snrm[row] = n; }
    }
    __syncthreads();
    if (t < 128) {
        float c = sdot[t] / (sqrtf(snrm[0]) * sqrtf(snrm[t]));
#pragma unroll
        for (int o = 16; o; o >>= 1) c += __shfl_xor_sync(0xffffffffu, c, o);
        if (lane == 0) red[t >> 5] = c;
    }
    __syncthreads();
    if (t == 0) g_s = (red[0] + red[1] + red[2] + red[3]) * (1.0f / 128.0f);
}

// ---------------------------------------------------------------------------
// One-time weight transpose: wT[n][k] = half(w[k][n])  (two 128x128 tables)
// ---------------------------------------------------------------------------
__global__ void k_prepw(const float* __restrict__ w1,
                        const float* __restrict__ w2) {
    int i = blockIdx.x * blockDim.x + threadIdx.x;   // 16384
    if (i >= 16384) return;
    int n = i >> 7, k = i & 127;
    ((__half*)g_w1t)[n * 128 + k] = __float2half_rn(w1[k * 128 + n]);
    ((__half*)g_w2t)[n * 128 + k] = __float2half_rn(w2[k * 128 + n]);
}

// ---------------------------------------------------------------------------
// fp32 -> fp16 table convert (x)
// ---------------------------------------------------------------------------
__global__ void k_tohalf(const float4* __restrict__ src,
                         uint2* __restrict__ dst, int n4) {
    int i = blockIdx.x * blockDim.x + threadIdx.x;
    if (i >= n4) return;
    float4 v = src[i];
    __half2 a = __floats2half2_rn(v.x, v.y);
    __half2 b = __floats2half2_rn(v.z, v.w);
    dst[i] = make_uint2(*(uint32_t*)&a, *(uint32_t*)&b);
}

// ---------------------------------------------------------------------------
// Masked-mean gather over fp16 rows. One warp/row; lane owns 4 cols.
// ---------------------------------------------------------------------------
template <int ARITY, bool OUTF32>
__global__ void k_gather_h(const uint2* __restrict__ src,
                           const int* __restrict__ idxmat,
                           void* __restrict__ dstv, int rows) {
    int w = (blockIdx.x * blockDim.x + threadIdx.x) >> 5;
    int lane = threadIdx.x & 31;
    if (w >= rows) return;

    int idx = 0;
    if (lane < ARITY) idx = idxmat[w * ARITY + lane];
    unsigned on = __ballot_sync(0xffffffffu, (lane < ARITY) && (idx > 0));
    int cnt = __popc(on);
    float wn = cnt ? (1.0f / (float)cnt) : (1.0f / (float)ARITY);

    float4 acc = make_float4(0.f, 0.f, 0.f, 0.f);
#pragma unroll
    for (int a = 0; a < ARITY; a++) {
        int ia = __shfl_sync(0xffffffffu, idx, a);
        float wa = cnt ? (((on >> a) & 1u) ? wn : 0.0f) : wn;
        uint2 u = src[ia * 32 + lane];
        float2 f0 = __half22float2(*(__half2*)&u.x);
        float2 f1 = __half22float2(*(__half2*)&u.y);
        acc.x += wa * f0.x; acc.y += wa * f0.y;
        acc.z += wa * f1.x; acc.w += wa * f1.y;
    }
    if (OUTF32) {
        ((float4*)dstv)[w * 32 + lane] = acc;
    } else {
        __half2 a = __floats2half2_rn(acc.x, acc.y);
        __half2 b = __floats2half2_rn(acc.z, acc.w);
        ((uint2*)dstv)[w * 32 + lane] = make_uint2(*(uint32_t*)&a, *(uint32_t*)&b);
    }
}

// ---------------------------------------------------------------------------
// Fused dual GEMM (fp16 m16n8k16 + ldmatrix): e1 = relu(s*A@W1)@W2
// 128 rows/CTA, 512 threads (16 warps), warp tile 32x32, 2 CTAs/SM.
//   sA [128][136]h, sW1t/sW2t [n=128][k=136]h  -> 104.4 KB
// ---------------------------------------------------------------------------
#define PH 136
#define SA_HALFS (128 * PH)
#define SMEM_TOTAL (3 * SA_HALFS * 2)

__device__ __forceinline__ void do_gemm_ldsm(uint32_t aA0, uint32_t aA1,
                                             uint32_t bA0, uint32_t bA1,
                                             float acc[2][4][4]) {
#pragma unroll
    for (int k0 = 0; k0 < 128; k0 += 16) {
        uint32_t a0[4], a1[4], b0[4], b1[4];
        ldsm_x4(a0, aA0 + k0 * 2);
        ldsm_x4(a1, aA1 + k0 * 2);
        ldsm_x4(b0, bA0 + k0 * 2);
        ldsm_x4(b1, bA1 + k0 * 2);
        // b regs: {ns_even.b0, ns_odd.b0, ns_even.b1, ns_odd.b1}
        mma16(acc[0][0], a0, b0[0], b0[2]);
        mma16(acc[0][1], a0, b0[1], b0[3]);
        mma16(acc[0][2], a0, b1[0], b1[2]);
        mma16(acc[0][3], a0, b1[1], b1[3]);
        mma16(acc[1][0], a1, b0[0], b0[2]);
        mma16(acc[1][1], a1, b0[1], b0[3]);
        mma16(acc[1][2], a1, b1[0], b1[2]);
        mma16(acc[1][3], a1, b1[1], b1[3]);
    }
}

__global__ void __launch_bounds__(512, 2)
k_dualgemm(const uint2* __restrict__ Aeph, __half2* __restrict__ e1h, int M) {
    extern __shared__ __align__(16) __half smem[];
    __half* sA   = smem;
    __half* sW1t = smem + SA_HALFS;
    __half* sW2t = sW1t + SA_HALFS;

    int t = threadIdx.x;
    int w = t >> 5, lane = t & 31;
    int g = lane >> 2, tig = lane & 3;
    int row0 = blockIdx.x * 128;

    // ---- coalesced smem fills (8B each, conflict-free) ----
    for (int i = t; i < 4096; i += 512) {
        int r = i >> 5, c = i & 31;
        *(uint2*)&sW1t[r * PH + c * 4] = g_w1t[r * 32 + c];
        *(uint2*)&sW2t[r * PH + c * 4] = g_w2t[r * 32 + c];
        uint2 u = (row0 + r < M) ? Aeph[(size_t)(row0 + r) * 32 + c]
                                 : make_uint2(0u, 0u);
        *(uint2*)&sA[r * PH + c * 4] = u;
    }
    __syncthreads();

    int mrow0 = (w & 3) * 32;       // warp row strip
    int ncol0 = (w >> 2) * 32;      // warp col strip

    // ldmatrix lane addresses
    int mi = lane >> 3, ri = lane & 7;
    int rsel = (mi & 1) * 8 + ri;   // row within 16-row strip
    int ksel = (mi >> 1) * 8;       // k offset (0 or 8)
    uint32_t sA_s  = (uint32_t)__cvta_generic_to_shared(sA);
    uint32_t sW1_s = (uint32_t)__cvta_generic_to_shared(sW1t);
    uint32_t sW2_s = (uint32_t)__cvta_generic_to_shared(sW2t);
    uint32_t aA0 = sA_s + ((mrow0 + rsel) * PH + ksel) * 2;
    uint32_t aA1 = aA0 + 16 * PH * 2;
    uint32_t off_b = (uint32_t)(((ncol0 + rsel) * PH + ksel) * 2);
    uint32_t b1A0 = sW1_s + off_b, b1A1 = b1A0 + 16 * PH * 2;
    uint32_t b2A0 = sW2_s + off_b, b2A1 = b2A0 + 16 * PH * 2;

    float acc[2][4][4];
#pragma unroll
    for (int ms = 0; ms < 2; ms++)
#pragma unroll
        for (int ns = 0; ns < 4; ns++)
#pragma unroll
            for (int j = 0; j < 4; j++) acc[ms][ns][j] = 0.f;

    // ================= GEMM 1 =================
    do_gemm_ldsm(aA0, aA1, b1A0, b1A1, acc);

    float s_nw = g_s;
    __syncthreads();    // all warps done reading sA before overwrite

    // relu(s * acc) -> sA (fp16); acc fragment: (row g, col 2*tig) pattern
#pragma unroll
    for (int ms = 0; ms < 2; ms++) {
#pragma unroll
        for (int ns = 0; ns < 4; ns++) {
            int r0 = mrow0 + ms * 16 + g;
            int c0 = ncol0 + ns * 8 + 2 * tig;
            __half2 lo = __floats2half2_rn(fmaxf(acc[ms][ns][0] * s_nw, 0.f),
                                           fmaxf(acc[ms][ns][1] * s_nw, 0.f));
            __half2 hi = __floats2half2_rn(fmaxf(acc[ms][ns][2] * s_nw, 0.f),
                                           fmaxf(acc[ms][ns][3] * s_nw, 0.f));
            *(__half2*)&sA[r0 * PH + c0] = lo;
            *(__half2*)&sA[(r0 + 8) * PH + c0] = hi;
#pragma unroll
            for (int j = 0; j < 4; j++) acc[ms][ns][j] = 0.f;
        }
    }
    __syncthreads();

    // ================= GEMM 2 =================
    do_gemm_ldsm(aA0, aA1, b2A0, b2A1, acc);

    // write e1 (fp16)
#pragma unroll
    for (int ms = 0; ms < 2; ms++) {
#pragma unroll
        for (int ns = 0; ns < 4; ns++) {
            int r = row0 + mrow0 + ms * 16 + g;
            int c0 = ncol0 + ns * 8 + 2 * tig;
            if (r < M)
                e1h[(size_t)r * 64 + (c0 >> 1)] =
                    __floats2half2_rn(acc[ms][ns][0], acc[ms][ns][1]);
            if (r + 8 < M)
                e1h[(size_t)(r + 8) * 64 + (c0 >> 1)] =
                    __floats2half2_rn(acc[ms][ns][2], acc[ms][ns][3]);
        }
    }
}

// ---------------------------------------------------------------------------
extern "C" void kernel_launch(void* const* d_in, const int* in_sizes, int n_in,
                              void* d_out, int out_size) {
    const float* x    = (const float*)d_in[0];   // [100000,128]
    const int*   seq  = (const int*)d_in[1];     // [50000,32]
    const int*   useq = (const int*)d_in[2];     // [100000,16]
    const float* w1   = (const float*)d_in[4];   // [128,128]
    const float* w2   = (const float*)d_in[5];   // [128,128]
    const float* w3   = (const float*)d_in[6];   // [128,128]

    void *p_xh, *p_eph, *p_e1h;
    cudaGetSymbolAddress(&p_xh, g_xh);
    cudaGetSymbolAddress(&p_eph, g_eph);
    cudaGetSymbolAddress(&p_e1h, g_e1h);

    cudaFuncSetAttribute(k_dualgemm,
                         cudaFuncAttributeMaxDynamicSharedMemorySize,
                         SMEM_TOTAL);

    k_internw<<<1, 512>>>(w3);
    k_prepw<<<64, 256>>>(w1, w2);

    // x -> fp16 table
    {
        int n4 = N_NODESC * 32;
        k_tohalf<<<(n4 + 255) / 256, 256>>>((const float4*)x, (uint2*)p_xh, n4);
    }

    // edge_pre[e] = masked-mean_a x_h[seq[e,a]]  (fp32 accum, fp16 out)
    k_gather_h<32, false><<<(N_EDGES + 7) / 8, 256>>>(
        (const uint2*)p_xh, seq, p_eph, N_EDGES);

    // e1 = relu(s * edge_pre @ W1) @ W2   (fp16 mma + ldmatrix)
    k_dualgemm<<<TILES, 512, SMEM_TOTAL>>>((const uint2*)p_eph,
                                           (__half2*)p_e1h, N_EDGES);

    // out[n] = masked-mean_k e1_h[useq[n,k]]  (fp32 out)
    k_gather_h<16, true><<<(N_NODESC + 7) / 8, 256>>>(
        (const uint2*)p_e1h, useq, d_out, N_NODESC);
}

// round 14
// speedup vs baseline: 1.8372x; 1.0040x over previous
#include <cuda_runtime.h>
#include <cuda_fp16.h>
#include <cstdint>

#define N_EDGES   50000
#define N_NODESC  100000
#define TILES     ((N_EDGES + 127) / 128)     // 391

// ---------------- device scratch (allocation-free) ----------------
__device__ float  g_s;
__device__ uint2  g_xh[N_NODESC * 32];        // x as fp16 [100000,128]
__device__ uint2  g_e1h[N_EDGES * 32];        // e1 fp16 [50000,128]
__device__ uint2  g_w1t[128 * 32];            // W1^T fp16 [n][k]
__device__ uint2  g_w2t[128 * 32];            // W2^T fp16 [n][k]

// ---------------- mma / ldmatrix helpers ----------------
__device__ __forceinline__ void mma16(float* c, const uint32_t* a,
                                      uint32_t b0, uint32_t b1) {
    asm volatile(
        "mma.sync.aligned.m16n8k16.row.col.f32.f16.f16.f32 "
        "{%0,%1,%2,%3},{%4,%5,%6,%7},{%8,%9},{%0,%1,%2,%3};"
        : "+f"(c[0]), "+f"(c[1]), "+f"(c[2]), "+f"(c[3])
        : "r"(a[0]), "r"(a[1]), "r"(a[2]), "r"(a[3]), "r"(b0), "r"(b1));
}
__device__ __forceinline__ void ldsm_x4(uint32_t* r, uint32_t addr) {
    asm volatile(
        "ldmatrix.sync.aligned.m8n8.x4.shared.b16 {%0,%1,%2,%3}, [%4];"
        : "=r"(r[0]), "=r"(r[1]), "=r"(r[2]), "=r"(r[3]) : "r"(addr));
}

// ---------------------------------------------------------------------------
// Prep: blocks 0..31 transpose W1/W2 to fp16 [n][k]; block 32 computes
// inter_nw = mean_i cos(w3[i], w3[0]).   512 threads per block.
// ---------------------------------------------------------------------------
__global__ void k_prep(const float* __restrict__ w1,
                       const float* __restrict__ w2,
                       const float* __restrict__ w3) {
    if (blockIdx.x < 32) {
        int i = blockIdx.x * 512 + threadIdx.x;   // 16384 = 128*128
        int n = i >> 7, k = i & 127;
        ((__half*)g_w1t)[n * 128 + k] = __float2half_rn(w1[k * 128 + n]);
        ((__half*)g_w2t)[n * 128 + k] = __float2half_rn(w2[k * 128 + n]);
        return;
    }
    __shared__ float sdot[128], snrm[128], red[4];
    int t = threadIdx.x, w = t >> 5, lane = t & 31;
    for (int row = w; row < 128; row += 16) {
        float d = 0.f, n = 0.f;
#pragma unroll
        for (int jj = 0; jj < 4; jj++) {
            int j = jj * 32 + lane;
            float v = w3[row * 128 + j];
            d += v * w3[j];
            n += v * v;
        }
#pragma unroll
        for (int o = 16; o; o >>= 1) {
            d += __shfl_xor_sync(0xffffffffu, d, o);
            n += __shfl_xor_sync(0xffffffffu, n, o);
        }
        if (lane == 0) { sdot[row] = d; snrm[row] = n; }
    }
    __syncthreads();
    if (t < 128) {
        float c = sdot[t] / (sqrtf(snrm[0]) * sqrtf(snrm[t]));
#pragma unroll
        for (int o = 16; o; o >>= 1) c += __shfl_xor_sync(0xffffffffu, c, o);
        if (lane == 0) red[t >> 5] = c;
    }
    __syncthreads();
    if (t == 0) g_s = (red[0] + red[1] + red[2] + red[3]) * (1.0f / 128.0f);
}

// ---------------------------------------------------------------------------
// fp32 -> fp16 table convert (x)
// ---------------------------------------------------------------------------
__global__ void k_tohalf(const float4* __restrict__ src,
                         uint2* __restrict__ dst, int n4) {
    int i = blockIdx.x * blockDim.x + threadIdx.x;
    if (i >= n4) return;
    float4 v = src[i];
    __half2 a = __floats2half2_rn(v.x, v.y);
    __half2 b = __floats2half2_rn(v.z, v.w);
    dst[i] = make_uint2(*(uint32_t*)&a, *(uint32_t*)&b);
}

// ---------------------------------------------------------------------------
// Final masked-mean gather over fp16 e1 rows -> fp32 out.
// ---------------------------------------------------------------------------
__global__ void k_gather16(const uint2* __restrict__ src,
                           const int* __restrict__ idxmat,
                           float4* __restrict__ dst, int rows) {
    int w = (blockIdx.x * blockDim.x + threadIdx.x) >> 5;
    int lane = threadIdx.x & 31;
    if (w >= rows) return;

    int idx = 0;
    if (lane < 16) idx = idxmat[w * 16 + lane];
    unsigned on = __ballot_sync(0xffffffffu, (lane < 16) && (idx > 0));
    int cnt = __popc(on);
    float wn = cnt ? (1.0f / (float)cnt) : (1.0f / 16.0f);

    float4 acc = make_float4(0.f, 0.f, 0.f, 0.f);
#pragma unroll
    for (int a = 0; a < 16; a++) {
        int ia = __shfl_sync(0xffffffffu, idx, a);
        float wa = cnt ? (((on >> a) & 1u) ? wn : 0.0f) : wn;
        uint2 u = src[ia * 32 + lane];
        float2 f0 = __half22float2(*(__half2*)&u.x);
        float2 f1 = __half22float2(*(__half2*)&u.y);
        acc.x += wa * f0.x; acc.y += wa * f0.y;
        acc.z += wa * f1.x; acc.w += wa * f1.y;
    }
    dst[w * 32 + lane] = acc;
}

// ---------------------------------------------------------------------------
// Fused: gather(x_h, seq) -> sA, then e1 = relu(s*A@W1)@W2 (fp16 mma+ldsm)
// 128 rows/CTA, 512 threads (16 warps), warp tile 32x32, 2 CTAs/SM.
//   sA [128][136]h, sW1t/sW2t [n=128][k=136]h  -> 104.4 KB
// ---------------------------------------------------------------------------
#define PH 136
#define SA_HALFS (128 * PH)
#define SMEM_TOTAL (3 * SA_HALFS * 2)

__device__ __forceinline__ void do_gemm_ldsm(uint32_t aA0, uint32_t aA1,
                                             uint32_t bA0, uint32_t bA1,
                                             float acc[2][4][4]) {
#pragma unroll
    for (int k0 = 0; k0 < 128; k0 += 16) {
        uint32_t a0[4], a1[4], b0[4], b1[4];
        ldsm_x4(a0, aA0 + k0 * 2);
        ldsm_x4(a1, aA1 + k0 * 2);
        ldsm_x4(b0, bA0 + k0 * 2);
        ldsm_x4(b1, bA1 + k0 * 2);
        mma16(acc[0][0], a0, b0[0], b0[2]);
        mma16(acc[0][1], a0, b0[1], b0[3]);
        mma16(acc[0][2], a0, b1[0], b1[2]);
        mma16(acc[0][3], a0, b1[1], b1[3]);
        mma16(acc[1][0], a1, b0[0], b0[2]);
        mma16(acc[1][1], a1, b0[1], b0[3]);
        mma16(acc[1][2], a1, b1[0], b1[2]);
        mma16(acc[1][3], a1, b1[1], b1[3]);
    }
}

__global__ void __launch_bounds__(512, 2)
k_fused(const uint2* __restrict__ xh, const int* __restrict__ seq,
        __half2* __restrict__ e1h, int M) {
    extern __shared__ __align__(16) __half smem[];
    __half* sA   = smem;
    __half* sW1t = smem + SA_HALFS;
    __half* sW2t = sW1t + SA_HALFS;

    int t = threadIdx.x;
    int w = t >> 5, lane = t & 31;
    int g = lane >> 2, tig = lane & 3;
    int row0 = blockIdx.x * 128;

    // ---- weight smem fills (coalesced 8B, conflict-free) ----
    for (int i = t; i < 4096; i += 512) {
        int r = i >> 5, c = i & 31;
        *(uint2*)&sW1t[r * PH + c * 4] = g_w1t[r * 32 + c];
        *(uint2*)&sW2t[r * PH + c * 4] = g_w2t[r * 32 + c];
    }

    // ---- phase 1: gather 128 edge rows into sA (one warp per row, x8) ----
#pragma unroll
    for (int it = 0; it < 8; it++) {
        int rr = it * 16 + w;                 // 0..127
        int row = row0 + rr;
        int idx = 0;
        if (row < M) idx = seq[row * 32 + lane];
        unsigned on = __ballot_sync(0xffffffffu, idx > 0);
        int cnt = __popc(on);
        // row >= M: idx==0 everywhere -> on==0 -> falls to uniform; but we
        // want zeros for tail rows; handle below with zfill=0 when row>=M.
        float wn = cnt ? (1.0f / (float)cnt) : 0.0f;
        float zfill = (cnt || row >= M) ? 0.0f : (1.0f / 32.0f);

        float4 acc = make_float4(0.f, 0.f, 0.f, 0.f);
#pragma unroll
        for (int a = 0; a < 32; a++) {
            int ia = __shfl_sync(0xffffffffu, idx, a);
            float wa = ((on >> a) & 1u) ? wn : zfill;
            uint2 u = xh[ia * 32 + lane];
            float2 f0 = __half22float2(*(__half2*)&u.x);
            float2 f1 = __half22float2(*(__half2*)&u.y);
            acc.x += wa * f0.x; acc.y += wa * f0.y;
            acc.z += wa * f1.x; acc.w += wa * f1.y;
        }
        __half2 h0 = __floats2half2_rn(acc.x, acc.y);
        __half2 h1 = __floats2half2_rn(acc.z, acc.w);
        *(uint2*)&sA[rr * PH + lane * 4] =
            make_uint2(*(uint32_t*)&h0, *(uint32_t*)&h1);
    }
    __syncthreads();

    int mrow0 = (w & 3) * 32;       // warp row strip
    int ncol0 = (w >> 2) * 32;      // warp col strip

    // ldmatrix lane addresses
    int mi = lane >> 3, ri = lane & 7;
    int rsel = (mi & 1) * 8 + ri;
    int ksel = (mi >> 1) * 8;
    uint32_t sA_s  = (uint32_t)__cvta_generic_to_shared(sA);
    uint32_t sW1_s = (uint32_t)__cvta_generic_to_shared(sW1t);
    uint32_t sW2_s = (uint32_t)__cvta_generic_to_shared(sW2t);
    uint32_t aA0 = sA_s + ((mrow0 + rsel) * PH + ksel) * 2;
    uint32_t aA1 = aA0 + 16 * PH * 2;
    uint32_t off_b = (uint32_t)(((ncol0 + rsel) * PH + ksel) * 2);
    uint32_t b1A0 = sW1_s + off_b, b1A1 = b1A0 + 16 * PH * 2;
    uint32_t b2A0 = sW2_s + off_b, b2A1 = b2A0 + 16 * PH * 2;

    float acc[2][4][4];
#pragma unroll
    for (int ms = 0; ms < 2; ms++)
#pragma unroll
        for (int ns = 0; ns < 4; ns++)
#pragma unroll
            for (int j = 0; j < 4; j++) acc[ms][ns][j] = 0.f;

    // ================= GEMM 1 =================
    do_gemm_ldsm(aA0, aA1, b1A0, b1A1, acc);

    float s_nw = g_s;
    __syncthreads();    // all warps done reading sA before overwrite

    // relu(s * acc) -> sA (fp16)
#pragma unroll
    for (int ms = 0; ms < 2; ms++) {
#pragma unroll
        for (int ns = 0; ns < 4; ns++) {
            int r0 = mrow0 + ms * 16 + g;
            int c0 = ncol0 + ns * 8 + 2 * tig;
            __half2 lo = __floats2half2_rn(fmaxf(acc[ms][ns][0] * s_nw, 0.f),
                                           fmaxf(acc[ms][ns][1] * s_nw, 0.f));
            __half2 hi = __floats2half2_rn(fmaxf(acc[ms][ns][2] * s_nw, 0.f),
                                           fmaxf(acc[ms][ns][3] * s_nw, 0.f));
            *(__half2*)&sA[r0 * PH + c0] = lo;
            *(__half2*)&sA[(r0 + 8) * PH + c0] = hi;
#pragma unroll
            for (int j = 0; j < 4; j++) acc[ms][ns][j] = 0.f;
        }
    }
    __syncthreads();

    // ================= GEMM 2 =================
    do_gemm_ldsm(aA0, aA1, b2A0, b2A1, acc);

    // write e1 (fp16)
#pragma unroll
    for (int ms = 0; ms < 2; ms++) {
#pragma unroll
        for (int ns = 0; ns < 4; ns++) {
            int r = row0 + mrow0 + ms * 16 + g;
            int c0 = ncol0 + ns * 8 + 2 * tig;
            if (r < M)
                e1h[(size_t)r * 64 + (c0 >> 1)] =
                    __floats2half2_rn(acc[ms][ns][0], acc[ms][ns][1]);
            if (r + 8 < M)
                e1h[(size_t)(r + 8) * 64 + (c0 >> 1)] =
                    __floats2half2_rn(acc[ms][ns][2], acc[ms][ns][3]);
        }
    }
}

// ---------------------------------------------------------------------------
extern "C" void kernel_launch(void* const* d_in, const int* in_sizes, int n_in,
                              void* d_out, int out_size) {
    const float* x    = (const float*)d_in[0];   // [100000,128]
    const int*   seq  = (const int*)d_in[1];     // [50000,32]
    const int*   useq = (const int*)d_in[2];     // [100000,16]
    const float* w1   = (const float*)d_in[4];   // [128,128]
    const float* w2   = (const float*)d_in[5];   // [128,128]
    const float* w3   = (const float*)d_in[6];   // [128,128]

    void *p_xh, *p_e1h;
    cudaGetSymbolAddress(&p_xh, g_xh);
    cudaGetSymbolAddress(&p_e1h, g_e1h);

    cudaFuncSetAttribute(k_fused, cudaFuncAttributeMaxDynamicSharedMemorySize,
                         SMEM_TOTAL);

    // weights transpose + inter_nw
    k_prep<<<33, 512>>>(w1, w2, w3);

    // x -> fp16 table
    {
        int n4 = N_NODESC * 32;
        k_tohalf<<<(n4 + 255) / 256, 256>>>((const float4*)x, (uint2*)p_xh, n4);
    }

    // gather32 + dual GEMM fused
    k_fused<<<TILES, 512, SMEM_TOTAL>>>((const uint2*)p_xh, seq,
                                        (__half2*)p_e1h, N_EDGES);

    // out[n] = masked-mean_k e1_h[useq[n,k]]
    k_gather16<<<(N_NODESC + 7) / 8, 256>>>((const uint2*)p_e1h, useq,
                                            (float4*)d_out, N_NODESC);
}

// round 15
// speedup vs baseline: 2.0803x; 1.1323x over previous
#include <cuda_runtime.h>
#include <cuda_fp16.h>
#include <cstdint>

#define N_EDGES   50000
#define N_NODESC  100000
#define TILES     ((N_EDGES + 127) / 128)     // 391

// ---------------- device scratch (allocation-free) ----------------
__device__ float  g_s;
__device__ uint2  g_xh[N_NODESC * 32];        // x as fp16 [100000,128]
__device__ uint2  g_e1h[N_EDGES * 32];        // e1 fp16 [50000,128]
__device__ uint2  g_w1t[128 * 32];            // W1^T fp16 [n][k]
__device__ uint2  g_w2t[128 * 32];            // W2^T fp16 [n][k]

// ---------------- mma / ldmatrix helpers ----------------
__device__ __forceinline__ void mma16(float* c, const uint32_t* a,
                                      uint32_t b0, uint32_t b1) {
    asm volatile(
        "mma.sync.aligned.m16n8k16.row.col.f32.f16.f16.f32 "
        "{%0,%1,%2,%3},{%4,%5,%6,%7},{%8,%9},{%0,%1,%2,%3};"
        : "+f"(c[0]), "+f"(c[1]), "+f"(c[2]), "+f"(c[3])
        : "r"(a[0]), "r"(a[1]), "r"(a[2]), "r"(a[3]), "r"(b0), "r"(b1));
}
__device__ __forceinline__ void ldsm_x4(uint32_t* r, uint32_t addr) {
    asm volatile(
        "ldmatrix.sync.aligned.m8n8.x4.shared.b16 {%0,%1,%2,%3}, [%4];"
        : "=r"(r[0]), "=r"(r[1]), "=r"(r[2]), "=r"(r[3]) : "r"(addr));
}

// ---------------------------------------------------------------------------
// Prep (one launch):
//   blocks [0,32): W1/W2 transpose -> fp16 [n][k]
//   block  32    : inter_nw = mean_i cos(w3[i], w3[0])
//   blocks [33..): x -> fp16 table (6250 blocks x 512 = 3.2M uint2)
// ---------------------------------------------------------------------------
__global__ void k_prep(const float* __restrict__ w1,
                       const float* __restrict__ w2,
                       const float* __restrict__ w3,
                       const float4* __restrict__ x) {
    if (blockIdx.x < 32) {
        int i = blockIdx.x * 512 + threadIdx.x;   // 16384 = 128*128
        int n = i >> 7, k = i & 127;
        ((__half*)g_w1t)[n * 128 + k] = __float2half_rn(w1[k * 128 + n]);
        ((__half*)g_w2t)[n * 128 + k] = __float2half_rn(w2[k * 128 + n]);
        return;
    }
    if (blockIdx.x >= 33) {
        int i = (blockIdx.x - 33) * 512 + threadIdx.x;   // < 3,200,000
        float4 v = x[i];
        __half2 a = __floats2half2_rn(v.x, v.y);
        __half2 b = __floats2half2_rn(v.z, v.w);
        g_xh[i] = make_uint2(*(uint32_t*)&a, *(uint32_t*)&b);
        return;
    }
    __shared__ float sdot[128], snrm[128], red[4];
    int t = threadIdx.x, w = t >> 5, lane = t & 31;
    for (int row = w; row < 128; row += 16) {
        float d = 0.f, n = 0.f;
#pragma unroll
        for (int jj = 0; jj < 4; jj++) {
            int j = jj * 32 + lane;
            float v = w3[row * 128 + j];
            d += v * w3[j];
            n += v * v;
        }
#pragma unroll
        for (int o = 16; o; o >>= 1) {
            d += __shfl_xor_sync(0xffffffffu, d, o);
            n += __shfl_xor_sync(0xffffffffu, n, o);
        }
        if (lane == 0) { sdot[row] = d; snrm[row] = n; }
    }
    __syncthreads();
    if (t < 128) {
        float c = sdot[t] / (sqrtf(snrm[0]) * sqrtf(snrm[t]));
#pragma unroll
        for (int o = 16; o; o >>= 1) c += __shfl_xor_sync(0xffffffffu, c, o);
        if (lane == 0) red[t >> 5] = c;
    }
    __syncthreads();
    if (t == 0) g_s = (red[0] + red[1] + red[2] + red[3]) * (1.0f / 128.0f);
}

// ---------------------------------------------------------------------------
// Final masked-mean gather (fp16 chains x4, fp32 combine) -> fp32 out.
// ---------------------------------------------------------------------------
__global__ void k_gather16(const uint2* __restrict__ src,
                           const int* __restrict__ idxmat,
                           float4* __restrict__ dst, int rows) {
    int w = (blockIdx.x * blockDim.x + threadIdx.x) >> 5;
    int lane = threadIdx.x & 31;
    if (w >= rows) return;

    int idx = 0;
    if (lane < 16) idx = idxmat[w * 16 + lane];
    unsigned on = __ballot_sync(0xffffffffu, (lane < 16) && (idx > 0));
    int cnt = __popc(on);
    float wn = cnt ? (1.0f / (float)cnt) : (1.0f / 16.0f);
    if (cnt == 0) on = 0xFFFFu;
    __half2 wn2 = __half2half2(__float2half_rn(wn));
    const __half2 z2 = __half2half2(__ushort_as_half(0));

    __half2 acc[4][2];
#pragma unroll
    for (int j = 0; j < 4; j++) { acc[j][0] = z2; acc[j][1] = z2; }

#pragma unroll
    for (int a = 0; a < 16; a++) {
        int ia = __shfl_sync(0xffffffffu, idx, a);
        __half2 wa = ((on >> a) & 1u) ? wn2 : z2;
        uint2 u = src[ia * 32 + lane];
        acc[a & 3][0] = __hfma2(wa, *(__half2*)&u.x, acc[a & 3][0]);
        acc[a & 3][1] = __hfma2(wa, *(__half2*)&u.y, acc[a & 3][1]);
    }
    float2 c01 = __half22float2(acc[0][0]);
    float2 c23 = __half22float2(acc[0][1]);
#pragma unroll
    for (int j = 1; j < 4; j++) {
        float2 f0 = __half22float2(acc[j][0]);
        float2 f1 = __half22float2(acc[j][1]);
        c01.x += f0.x; c01.y += f0.y;
        c23.x += f1.x; c23.y += f1.y;
    }
    dst[w * 32 + lane] = make_float4(c01.x, c01.y, c23.x, c23.y);
}

// ---------------------------------------------------------------------------
// Fused: gather(x_h, seq) -> sA, then e1 = relu(s*A@W1)@W2 (fp16 mma+ldsm)
// 128 rows/CTA, 512 threads (16 warps), warp tile 32x32, 2 CTAs/SM.
// ---------------------------------------------------------------------------
#define PH 136
#define SA_HALFS (128 * PH)
#define SMEM_TOTAL (3 * SA_HALFS * 2)

__device__ __forceinline__ void do_gemm_ldsm(uint32_t aA0, uint32_t aA1,
                                             uint32_t bA0, uint32_t bA1,
                                             float acc[2][4][4]) {
#pragma unroll
    for (int k0 = 0; k0 < 128; k0 += 16) {
        uint32_t a0[4], a1[4], b0[4], b1[4];
        ldsm_x4(a0, aA0 + k0 * 2);
        ldsm_x4(a1, aA1 + k0 * 2);
        ldsm_x4(b0, bA0 + k0 * 2);
        ldsm_x4(b1, bA1 + k0 * 2);
        mma16(acc[0][0], a0, b0[0], b0[2]);
        mma16(acc[0][1], a0, b0[1], b0[3]);
        mma16(acc[0][2], a0, b1[0], b1[2]);
        mma16(acc[0][3], a0, b1[1], b1[3]);
        mma16(acc[1][0], a1, b0[0], b0[2]);
        mma16(acc[1][1], a1, b0[1], b0[3]);
        mma16(acc[1][2], a1, b1[0], b1[2]);
        mma16(acc[1][3], a1, b1[1], b1[3]);
    }
}

__global__ void __launch_bounds__(512, 2)
k_fused(const uint2* __restrict__ xh, const int* __restrict__ seq,
        __half2* __restrict__ e1h, int M) {
    extern __shared__ __align__(16) __half smem[];
    __half* sA   = smem;
    __half* sW1t = smem + SA_HALFS;
    __half* sW2t = sW1t + SA_HALFS;

    int t = threadIdx.x;
    int w = t >> 5, lane = t & 31;
    int g = lane >> 2, tig = lane & 3;
    int row0 = blockIdx.x * 128;

    // ---- weight smem fills (coalesced 8B, conflict-free) ----
    for (int i = t; i < 4096; i += 512) {
        int r = i >> 5, c = i & 31;
        *(uint2*)&sW1t[r * PH + c * 4] = g_w1t[r * 32 + c];
        *(uint2*)&sW2t[r * PH + c * 4] = g_w2t[r * 32 + c];
    }

    // ---- phase 1: gather 128 edge rows into sA (one warp/row, x8) ----
    const __half2 z2 = __half2half2(__ushort_as_half(0));
#pragma unroll
    for (int it = 0; it < 8; it++) {
        int rr = it * 16 + w;                 // 0..127
        int row = row0 + rr;
        int idx = 0;
        if (row < M) idx = seq[row * 32 + lane];
        unsigned on = __ballot_sync(0xffffffffu, idx > 0);
        int cnt = __popc(on);
        float wn = cnt ? (1.0f / (float)cnt) : (1.0f / 32.0f);
        if (cnt == 0 && row < M) on = 0xFFFFFFFFu;   // tail rows stay zero
        __half2 wn2 = __half2half2(__float2half_rn(wn));

        __half2 acc[8][2];
#pragma unroll
        for (int j = 0; j < 8; j++) { acc[j][0] = z2; acc[j][1] = z2; }
#pragma unroll
        for (int a = 0; a < 32; a++) {
            int ia = __shfl_sync(0xffffffffu, idx, a);
            __half2 wa = ((on >> a) & 1u) ? wn2 : z2;
            uint2 u = xh[ia * 32 + lane];
            acc[a & 7][0] = __hfma2(wa, *(__half2*)&u.x, acc[a & 7][0]);
            acc[a & 7][1] = __hfma2(wa, *(__half2*)&u.y, acc[a & 7][1]);
        }
        float2 c01 = __half22float2(acc[0][0]);
        float2 c23 = __half22float2(acc[0][1]);
#pragma unroll
        for (int j = 1; j < 8; j++) {
            float2 f0 = __half22float2(acc[j][0]);
            float2 f1 = __half22float2(acc[j][1]);
            c01.x += f0.x; c01.y += f0.y;
            c23.x += f1.x; c23.y += f1.y;
        }
        __half2 h0 = __floats2half2_rn(c01.x, c01.y);
        __half2 h1 = __floats2half2_rn(c23.x, c23.y);
        *(uint2*)&sA[rr * PH + lane * 4] =
            make_uint2(*(uint32_t*)&h0, *(uint32_t*)&h1);
    }
    __syncthreads();

    int mrow0 = (w & 3) * 32;       // warp row strip
    int ncol0 = (w >> 2) * 32;      // warp col strip

    // ldmatrix lane addresses
    int mi = lane >> 3, ri = lane & 7;
    int rsel = (mi & 1) * 8 + ri;
    int ksel = (mi >> 1) * 8;
    uint32_t sA_s  = (uint32_t)__cvta_generic_to_shared(sA);
    uint32_t sW1_s = (uint32_t)__cvta_generic_to_shared(sW1t);
    uint32_t sW2_s = (uint32_t)__cvta_generic_to_shared(sW2t);
    uint32_t aA0 = sA_s + ((mrow0 + rsel) * PH + ksel) * 2;
    uint32_t aA1 = aA0 + 16 * PH * 2;
    uint32_t off_b = (uint32_t)(((ncol0 + rsel) * PH + ksel) * 2);
    uint32_t b1A0 = sW1_s + off_b, b1A1 = b1A0 + 16 * PH * 2;
    uint32_t b2A0 = sW2_s + off_b, b2A1 = b2A0 + 16 * PH * 2;

    float acc[2][4][4];
#pragma unroll
    for (int ms = 0; ms < 2; ms++)
#pragma unroll
        for (int ns = 0; ns < 4; ns++)
#pragma unroll
            for (int j = 0; j < 4; j++) acc[ms][ns][j] = 0.f;

    // ================= GEMM 1 =================
    do_gemm_ldsm(aA0, aA1, b1A0, b1A1, acc);

    float s_nw = g_s;
    __syncthreads();    // all warps done reading sA before overwrite

    // relu(s * acc) -> sA (fp16)
#pragma unroll
    for (int ms = 0; ms < 2; ms++) {
#pragma unroll
        for (int ns = 0; ns < 4; ns++) {
            int r0 = mrow0 + ms * 16 + g;
            int c0 = ncol0 + ns * 8 + 2 * tig;
            __half2 lo = __floats2half2_rn(fmaxf(acc[ms][ns][0] * s_nw, 0.f),
                                           fmaxf(acc[ms][ns][1] * s_nw, 0.f));
            __half2 hi = __floats2half2_rn(fmaxf(acc[ms][ns][2] * s_nw, 0.f),
                                           fmaxf(acc[ms][ns][3] * s_nw, 0.f));
            *(__half2*)&sA[r0 * PH + c0] = lo;
            *(__half2*)&sA[(r0 + 8) * PH + c0] = hi;
#pragma unroll
            for (int j = 0; j < 4; j++) acc[ms][ns][j] = 0.f;
        }
    }
    __syncthreads();

    // ================= GEMM 2 =================
    do_gemm_ldsm(aA0, aA1, b2A0, b2A1, acc);

    // write e1 (fp16)
#pragma unroll
    for (int ms = 0; ms < 2; ms++) {
#pragma unroll
        for (int ns = 0; ns < 4; ns++) {
            int r = row0 + mrow0 + ms * 16 + g;
            int c0 = ncol0 + ns * 8 + 2 * tig;
            if (r < M)
                e1h[(size_t)r * 64 + (c0 >> 1)] =
                    __floats2half2_rn(acc[ms][ns][0], acc[ms][ns][1]);
            if (r + 8 < M)
                e1h[(size_t)(r + 8) * 64 + (c0 >> 1)] =
                    __floats2half2_rn(acc[ms][ns][2], acc[ms][ns][3]);
        }
    }
}

// ---------------------------------------------------------------------------
extern "C" void kernel_launch(void* const* d_in, const int* in_sizes, int n_in,
                              void* d_out, int out_size) {
    const float* x    = (const float*)d_in[0];   // [100000,128]
    const int*   seq  = (const int*)d_in[1];     // [50000,32]
    const int*   useq = (const int*)d_in[2];     // [100000,16]
    const float* w1   = (const float*)d_in[4];   // [128,128]
    const float* w2   = (const float*)d_in[5];   // [128,128]
    const float* w3   = (const float*)d_in[6];   // [128,128]

    void *p_xh, *p_e1h;
    cudaGetSymbolAddress(&p_xh, g_xh);
    cudaGetSymbolAddress(&p_e1h, g_e1h);

    cudaFuncSetAttribute(k_fused, cudaFuncAttributeMaxDynamicSharedMemorySize,
                         SMEM_TOTAL);

    // weights transpose + inter_nw + x->fp16 (one launch)
    k_prep<<<33 + 6250, 512>>>(w1, w2, w3, (const float4*)x);

    // gather32 + dual GEMM fused
    k_fused<<<TILES, 512, SMEM_TOTAL>>>((const uint2*)p_xh, seq,
                                        (__half2*)p_e1h, N_EDGES);

    // out[n] = masked-mean_k e1_h[useq[n,k]]
    k_gather16<<<(N_NODESC + 7) / 8, 256>>>((const uint2*)p_e1h, useq,
                                            (float4*)d_out, N_NODESC);
}

// round 16
// speedup vs baseline: 2.0947x; 1.0069x over previous
#include <cuda_runtime.h>
#include <cuda_fp16.h>
#include <cstdint>

#define N_EDGES   50000
#define N_NODESC  100000
#define TILES     ((N_EDGES + 127) / 128)     // 391

// ---------------- device scratch (allocation-free) ----------------
__device__ float  g_s;
__device__ uint2  g_xh[N_NODESC * 32];        // x as fp16 [100000,128]
__device__ uint2  g_e1h[N_EDGES * 32];        // e1 fp16 [50000,128]
__device__ uint2  g_w1t[128 * 32];            // W1^T fp16 [n][k]
__device__ uint2  g_w2t[128 * 32];            // W2^T fp16 [n][k]

// ---------------- mma / ldmatrix helpers ----------------
__device__ __forceinline__ void mma16(float* c, const uint32_t* a,
                                      uint32_t b0, uint32_t b1) {
    asm volatile(
        "mma.sync.aligned.m16n8k16.row.col.f32.f16.f16.f32 "
        "{%0,%1,%2,%3},{%4,%5,%6,%7},{%8,%9},{%0,%1,%2,%3};"
        : "+f"(c[0]), "+f"(c[1]), "+f"(c[2]), "+f"(c[3])
        : "r"(a[0]), "r"(a[1]), "r"(a[2]), "r"(a[3]), "r"(b0), "r"(b1));
}
__device__ __forceinline__ void ldsm_x4(uint32_t* r, uint32_t addr) {
    asm volatile(
        "ldmatrix.sync.aligned.m8n8.x4.shared.b16 {%0,%1,%2,%3}, [%4];"
        : "=r"(r[0]), "=r"(r[1]), "=r"(r[2]), "=r"(r[3]) : "r"(addr));
}

// ---------------------------------------------------------------------------
// Prep (one launch):
//   blocks [0,32): W1/W2 transpose -> fp16 [n][k]
//   block  32    : inter_nw = mean_i cos(w3[i], w3[0])
//   blocks [33..): x -> fp16, 4 elements/thread (MLP=4, coalesced)
// ---------------------------------------------------------------------------
#define XCONV_BLOCKS 1563     // 1563 * 512 * 4 = 3,201,024 >= 3,200,000

__global__ void k_prep(const float* __restrict__ w1,
                       const float* __restrict__ w2,
                       const float* __restrict__ w3,
                       const float4* __restrict__ x) {
    if (blockIdx.x < 32) {
        int i = blockIdx.x * 512 + threadIdx.x;   // 16384 = 128*128
        int n = i >> 7, k = i & 127;
        ((__half*)g_w1t)[n * 128 + k] = __float2half_rn(w1[k * 128 + n]);
        ((__half*)g_w2t)[n * 128 + k] = __float2half_rn(w2[k * 128 + n]);
        return;
    }
    if (blockIdx.x >= 33) {
        const int n4 = N_NODESC * 32;             // 3,200,000
        int base = (blockIdx.x - 33) * 2048 + threadIdx.x;
        float4 v[4];
        int ok[4];
#pragma unroll
        for (int j = 0; j < 4; j++) {
            int i = base + j * 512;
            ok[j] = (i < n4);
            v[j] = ok[j] ? x[i] : make_float4(0.f, 0.f, 0.f, 0.f);
        }
#pragma unroll
        for (int j = 0; j < 4; j++) {
            int i = base + j * 512;
            if (ok[j]) {
                __half2 a = __floats2half2_rn(v[j].x, v[j].y);
                __half2 b = __floats2half2_rn(v[j].z, v[j].w);
                g_xh[i] = make_uint2(*(uint32_t*)&a, *(uint32_t*)&b);
            }
        }
        return;
    }
    __shared__ float sdot[128], snrm[128], red[4];
    int t = threadIdx.x, w = t >> 5, lane = t & 31;
    for (int row = w; row < 128; row += 16) {
        float d = 0.f, n = 0.f;
#pragma unroll
        for (int jj = 0; jj < 4; jj++) {
            int j = jj * 32 + lane;
            float v = w3[row * 128 + j];
            d += v * w3[j];
            n += v * v;
        }
#pragma unroll
        for (int o = 16; o; o >>= 1) {
            d += __shfl_xor_sync(0xffffffffu, d, o);
            n += __shfl_xor_sync(0xffffffffu, n, o);
        }
        if (lane == 0) { sdot[row] = d; snrm[row] = n; }
    }
    __syncthreads();
    if (t < 128) {
        float c = sdot[t] / (sqrtf(snrm[0]) * sqrtf(snrm[t]));
#pragma unroll
        for (int o = 16; o; o >>= 1) c += __shfl_xor_sync(0xffffffffu, c, o);
        if (lane == 0) red[t >> 5] = c;
    }
    __syncthreads();
    if (t == 0) g_s = (red[0] + red[1] + red[2] + red[3]) * (1.0f / 128.0f);
}

// ---------------------------------------------------------------------------
// Final masked-mean gather: TWO output rows per warp.
// idxmat[r0*16 + lane] covers rows r0 (lanes 0-15) and r0+1 (lanes 16-31)
// in one coalesced load. fp16 chains x4 per row, fp32 combine.
// ---------------------------------------------------------------------------
__global__ void k_gather16x2(const uint2* __restrict__ src,
                             const int* __restrict__ idxmat,
                             float4* __restrict__ dst, int rows) {
    int wg = (blockIdx.x * blockDim.x + threadIdx.x) >> 5;   // warp id
    int lane = threadIdx.x & 31;
    int r0 = wg * 2;
    if (r0 >= rows) return;

    int idx = idxmat[r0 * 16 + lane];          // both rows, coalesced
    unsigned on = __ballot_sync(0xffffffffu, idx > 0);
    unsigned on0 = on & 0xFFFFu, on1 = on >> 16;
    int cnt0 = __popc(on0), cnt1 = __popc(on1);
    float wnf0 = cnt0 ? (1.0f / (float)cnt0) : (1.0f / 16.0f);
    float wnf1 = cnt1 ? (1.0f / (float)cnt1) : (1.0f / 16.0f);
    if (cnt0 == 0) on0 = 0xFFFFu;
    if (cnt1 == 0) on1 = 0xFFFFu;
    __half2 wn0 = __half2half2(__float2half_rn(wnf0));
    __half2 wn1 = __half2half2(__float2half_rn(wnf1));
    const __half2 z2 = __half2half2(__ushort_as_half(0));

    __half2 a0[4][2], a1[4][2];
#pragma unroll
    for (int j = 0; j < 4; j++) {
        a0[j][0] = z2; a0[j][1] = z2;
        a1[j][0] = z2; a1[j][1] = z2;
    }

#pragma unroll
    for (int a = 0; a < 16; a++) {
        int ia0 = __shfl_sync(0xffffffffu, idx, a);
        int ia1 = __shfl_sync(0xffffffffu, idx, a + 16);
        __half2 w0 = ((on0 >> a) & 1u) ? wn0 : z2;
        __half2 w1 = ((on1 >> a) & 1u) ? wn1 : z2;
        uint2 u0 = src[ia0 * 32 + lane];
        uint2 u1 = src[ia1 * 32 + lane];
        a0[a & 3][0] = __hfma2(w0, *(__half2*)&u0.x, a0[a & 3][0]);
        a0[a & 3][1] = __hfma2(w0, *(__half2*)&u0.y, a0[a & 3][1]);
        a1[a & 3][0] = __hfma2(w1, *(__half2*)&u1.x, a1[a & 3][0]);
        a1[a & 3][1] = __hfma2(w1, *(__half2*)&u1.y, a1[a & 3][1]);
    }
    float2 p01 = __half22float2(a0[0][0]);
    float2 p23 = __half22float2(a0[0][1]);
    float2 q01 = __half22float2(a1[0][0]);
    float2 q23 = __half22float2(a1[0][1]);
#pragma unroll
    for (int j = 1; j < 4; j++) {
        float2 f;
        f = __half22float2(a0[j][0]); p01.x += f.x; p01.y += f.y;
        f = __half22float2(a0[j][1]); p23.x += f.x; p23.y += f.y;
        f = __half22float2(a1[j][0]); q01.x += f.x; q01.y += f.y;
        f = __half22float2(a1[j][1]); q23.x += f.x; q23.y += f.y;
    }
    dst[r0 * 32 + lane] = make_float4(p01.x, p01.y, p23.x, p23.y);
    if (r0 + 1 < rows)
        dst[(r0 + 1) * 32 + lane] = make_float4(q01.x, q01.y, q23.x, q23.y);
}

// ---------------------------------------------------------------------------
// Fused: gather(x_h, seq) -> sA, then e1 = relu(s*A@W1)@W2 (fp16 mma+ldsm)
// 128 rows/CTA, 512 threads (16 warps), warp tile 32x32, 2 CTAs/SM.
// ---------------------------------------------------------------------------
#define PH 136
#define SA_HALFS (128 * PH)
#define SMEM_TOTAL (3 * SA_HALFS * 2)

__device__ __forceinline__ void do_gemm_ldsm(uint32_t aA0, uint32_t aA1,
                                             uint32_t bA0, uint32_t bA1,
                                             float acc[2][4][4]) {
#pragma unroll
    for (int k0 = 0; k0 < 128; k0 += 16) {
        uint32_t a0[4], a1[4], b0[4], b1[4];
        ldsm_x4(a0, aA0 + k0 * 2);
        ldsm_x4(a1, aA1 + k0 * 2);
        ldsm_x4(b0, bA0 + k0 * 2);
        ldsm_x4(b1, bA1 + k0 * 2);
        mma16(acc[0][0], a0, b0[0], b0[2]);
        mma16(acc[0][1], a0, b0[1], b0[3]);
        mma16(acc[0][2], a0, b1[0], b1[2]);
        mma16(acc[0][3], a0, b1[1], b1[3]);
        mma16(acc[1][0], a1, b0[0], b0[2]);
        mma16(acc[1][1], a1, b0[1], b0[3]);
        mma16(acc[1][2], a1, b1[0], b1[2]);
        mma16(acc[1][3], a1, b1[1], b1[3]);
    }
}

__global__ void __launch_bounds__(512, 2)
k_fused(const uint2* __restrict__ xh, const int* __restrict__ seq,
        __half2* __restrict__ e1h, int M) {
    extern __shared__ __align__(16) __half smem[];
    __half* sA   = smem;
    __half* sW1t = smem + SA_HALFS;
    __half* sW2t = sW1t + SA_HALFS;

    int t = threadIdx.x;
    int w = t >> 5, lane = t & 31;
    int g = lane >> 2, tig = lane & 3;
    int row0 = blockIdx.x * 128;

    // ---- weight smem fills (coalesced 8B, conflict-free) ----
    for (int i = t; i < 4096; i += 512) {
        int r = i >> 5, c = i & 31;
        *(uint2*)&sW1t[r * PH + c * 4] = g_w1t[r * 32 + c];
        *(uint2*)&sW2t[r * PH + c * 4] = g_w2t[r * 32 + c];
    }

    // ---- phase 1: gather 128 edge rows into sA (one warp/row, x8) ----
    const __half2 z2 = __half2half2(__ushort_as_half(0));
#pragma unroll
    for (int it = 0; it < 8; it++) {
        int rr = it * 16 + w;                 // 0..127
        int row = row0 + rr;
        int idx = 0;
        if (row < M) idx = seq[row * 32 + lane];
        unsigned on = __ballot_sync(0xffffffffu, idx > 0);
        int cnt = __popc(on);
        float wn = cnt ? (1.0f / (float)cnt) : (1.0f / 32.0f);
        if (cnt == 0 && row < M) on = 0xFFFFFFFFu;   // tail rows stay zero
        __half2 wn2 = __half2half2(__float2half_rn(wn));

        __half2 acc[8][2];
#pragma unroll
        for (int j = 0; j < 8; j++) { acc[j][0] = z2; acc[j][1] = z2; }
#pragma unroll
        for (int a = 0; a < 32; a++) {
            int ia = __shfl_sync(0xffffffffu, idx, a);
            __half2 wa = ((on >> a) & 1u) ? wn2 : z2;
            uint2 u = xh[ia * 32 + lane];
            acc[a & 7][0] = __hfma2(wa, *(__half2*)&u.x, acc[a & 7][0]);
            acc[a & 7][1] = __hfma2(wa, *(__half2*)&u.y, acc[a & 7][1]);
        }
        float2 c01 = __half22float2(acc[0][0]);
        float2 c23 = __half22float2(acc[0][1]);
#pragma unroll
        for (int j = 1; j < 8; j++) {
            float2 f0 = __half22float2(acc[j][0]);
            float2 f1 = __half22float2(acc[j][1]);
            c01.x += f0.x; c01.y += f0.y;
            c23.x += f1.x; c23.y += f1.y;
        }
        __half2 h0 = __floats2half2_rn(c01.x, c01.y);
        __half2 h1 = __floats2half2_rn(c23.x, c23.y);
        *(uint2*)&sA[rr * PH + lane * 4] =
            make_uint2(*(uint32_t*)&h0, *(uint32_t*)&h1);
    }
    __syncthreads();

    int mrow0 = (w & 3) * 32;       // warp row strip
    int ncol0 = (w >> 2) * 32;      // warp col strip

    // ldmatrix lane addresses
    int mi = lane >> 3, ri = lane & 7;
    int rsel = (mi & 1) * 8 + ri;
    int ksel = (mi >> 1) * 8;
    uint32_t sA_s  = (uint32_t)__cvta_generic_to_shared(sA);
    uint32_t sW1_s = (uint32_t)__cvta_generic_to_shared(sW1t);
    uint32_t sW2_s = (uint32_t)__cvta_generic_to_shared(sW2t);
    uint32_t aA0 = sA_s + ((mrow0 + rsel) * PH + ksel) * 2;
    uint32_t aA1 = aA0 + 16 * PH * 2;
    uint32_t off_b = (uint32_t)(((ncol0 + rsel) * PH + ksel) * 2);
    uint32_t b1A0 = sW1_s + off_b, b1A1 = b1A0 + 16 * PH * 2;
    uint32_t b2A0 = sW2_s + off_b, b2A1 = b2A0 + 16 * PH * 2;

    float acc[2][4][4];
#pragma unroll
    for (int ms = 0; ms < 2; ms++)
#pragma unroll
        for (int ns = 0; ns < 4; ns++)
#pragma unroll
            for (int j = 0; j < 4; j++) acc[ms][ns][j] = 0.f;

    // ================= GEMM 1 =================
    do_gemm_ldsm(aA0, aA1, b1A0, b1A1, acc);

    float s_nw = g_s;
    __syncthreads();    // all warps done reading sA before overwrite

    // relu(s * acc) -> sA (fp16)
#pragma unroll
    for (int ms = 0; ms < 2; ms++) {
#pragma unroll
        for (int ns = 0; ns < 4; ns++) {
            int r0 = mrow0 + ms * 16 + g;
            int c0 = ncol0 + ns * 8 + 2 * tig;
            __half2 lo = __floats2half2_rn(fmaxf(acc[ms][ns][0] * s_nw, 0.f),
                                           fmaxf(acc[ms][ns][1] * s_nw, 0.f));
            __half2 hi = __floats2half2_rn(fmaxf(acc[ms][ns][2] * s_nw, 0.f),
                                           fmaxf(acc[ms][ns][3] * s_nw, 0.f));
            *(__half2*)&sA[r0 * PH + c0] = lo;
            *(__half2*)&sA[(r0 + 8) * PH + c0] = hi;
#pragma unroll
            for (int j = 0; j < 4; j++) acc[ms][ns][j] = 0.f;
        }
    }
    __syncthreads();

    // ================= GEMM 2 =================
    do_gemm_ldsm(aA0, aA1, b2A0, b2A1, acc);

    // write e1 (fp16)
#pragma unroll
    for (int ms = 0; ms < 2; ms++) {
#pragma unroll
        for (int ns = 0; ns < 4; ns++) {
            int r = row0 + mrow0 + ms * 16 + g;
            int c0 = ncol0 + ns * 8 + 2 * tig;
            if (r < M)
                e1h[(size_t)r * 64 + (c0 >> 1)] =
                    __floats2half2_rn(acc[ms][ns][0], acc[ms][ns][1]);
            if (r + 8 < M)
                e1h[(size_t)(r + 8) * 64 + (c0 >> 1)] =
                    __floats2half2_rn(acc[ms][ns][2], acc[ms][ns][3]);
        }
    }
}

// ---------------------------------------------------------------------------
extern "C" void kernel_launch(void* const* d_in, const int* in_sizes, int n_in,
                              void* d_out, int out_size) {
    const float* x    = (const float*)d_in[0];   // [100000,128]
    const int*   seq  = (const int*)d_in[1];     // [50000,32]
    const int*   useq = (const int*)d_in[2];     // [100000,16]
    const float* w1   = (const float*)d_in[4];   // [128,128]
    const float* w2   = (const float*)d_in[5];   // [128,128]
    const float* w3   = (const float*)d_in[6];   // [128,128]

    void *p_xh, *p_e1h;
    cudaGetSymbolAddress(&p_xh, g_xh);
    cudaGetSymbolAddress(&p_e1h, g_e1h);

    cudaFuncSetAttribute(k_fused, cudaFuncAttributeMaxDynamicSharedMemorySize,
                         SMEM_TOTAL);

    // weights transpose + inter_nw + x->fp16 (one launch, MLP=4 convert)
    k_prep<<<33 + XCONV_BLOCKS, 512>>>(w1, w2, w3, (const float4*)x);

    // gather32 + dual GEMM fused
    k_fused<<<TILES, 512, SMEM_TOTAL>>>((const uint2*)p_xh, seq,
                                        (__half2*)p_e1h, N_EDGES);

    // out[n] = masked-mean_k e1_h[useq[n,k]]  (2 rows/warp)
    k_gather16x2<<<(N_NODESC / 2 + 7) / 8, 256>>>((const uint2*)p_e1h, useq,
                                                  (float4*)d_out, N_NODESC);
}

// round 17
// speedup vs baseline: 2.1928x; 1.0468x over previous
#include <cuda_runtime.h>
#include <cuda_fp16.h>
#include <cstdint>

#define N_EDGES   50000
#define N_NODESC  100000
#define TILES     ((N_EDGES + 127) / 128)     // 391

// ---------------- device scratch (allocation-free) ----------------
__device__ float  g_s;
__device__ uint2  g_xh[N_NODESC * 32];        // x as fp16 [100000,128]
__device__ uint2  g_e1h[N_EDGES * 32];        // e1 fp16 [50000,128]
__device__ uint2  g_w1t[128 * 32];            // W1^T fp16 [n][k]
__device__ uint2  g_w2t[128 * 32];            // W2^T fp16 [n][k]

// ---------------- mma / ldmatrix helpers ----------------
__device__ __forceinline__ void mma16(float* c, const uint32_t* a,
                                      uint32_t b0, uint32_t b1) {
    asm volatile(
        "mma.sync.aligned.m16n8k16.row.col.f32.f16.f16.f32 "
        "{%0,%1,%2,%3},{%4,%5,%6,%7},{%8,%9},{%0,%1,%2,%3};"
        : "+f"(c[0]), "+f"(c[1]), "+f"(c[2]), "+f"(c[3])
        : "r"(a[0]), "r"(a[1]), "r"(a[2]), "r"(a[3]), "r"(b0), "r"(b1));
}
__device__ __forceinline__ void ldsm_x4(uint32_t* r, uint32_t addr) {
    asm volatile(
        "ldmatrix.sync.aligned.m8n8.x4.shared.b16 {%0,%1,%2,%3}, [%4];"
        : "=r"(r[0]), "=r"(r[1]), "=r"(r[2]), "=r"(r[3]) : "r"(addr));
}

// ---------------------------------------------------------------------------
// Prep (one launch):
//   blocks [0,32): W1/W2 transpose -> fp16 [n][k]
//   block  32    : inter_nw = mean_i cos(w3[i], w3[0])
//   blocks [33..): x -> fp16, 8 float4/thread (MLP=8, streaming reads)
// ---------------------------------------------------------------------------
#define XCONV_BLOCKS 782      // 782 * 512 * 8 = 3,203,072 >= 3,200,000

__global__ void k_prep(const float* __restrict__ w1,
                       const float* __restrict__ w2,
                       const float* __restrict__ w3,
                       const float4* __restrict__ x) {
    if (blockIdx.x < 32) {
        int i = blockIdx.x * 512 + threadIdx.x;   // 16384 = 128*128
        int n = i >> 7, k = i & 127;
        ((__half*)g_w1t)[n * 128 + k] = __float2half_rn(w1[k * 128 + n]);
        ((__half*)g_w2t)[n * 128 + k] = __float2half_rn(w2[k * 128 + n]);
        return;
    }
    if (blockIdx.x >= 33) {
        const int n4 = N_NODESC * 32;             // 3,200,000
        int base = (blockIdx.x - 33) * 4096 + threadIdx.x;
        float4 v[8];
        int ok[8];
#pragma unroll
        for (int j = 0; j < 8; j++) {
            int i = base + j * 512;
            ok[j] = (i < n4);
            v[j] = ok[j] ? __ldcs(&x[i]) : make_float4(0.f, 0.f, 0.f, 0.f);
        }
#pragma unroll
        for (int j = 0; j < 8; j++) {
            int i = base + j * 512;
            if (ok[j]) {
                __half2 a = __floats2half2_rn(v[j].x, v[j].y);
                __half2 b = __floats2half2_rn(v[j].z, v[j].w);
                g_xh[i] = make_uint2(*(uint32_t*)&a, *(uint32_t*)&b);
            }
        }
        return;
    }
    __shared__ float sdot[128], snrm[128], red[4];
    int t = threadIdx.x, w = t >> 5, lane = t & 31;
    for (int row = w; row < 128; row += 16) {
        float d = 0.f, n = 0.f;
#pragma unroll
        for (int jj = 0; jj < 4; jj++) {
            int j = jj * 32 + lane;
            float v = w3[row * 128 + j];
            d += v * w3[j];
            n += v * v;
        }
#pragma unroll
        for (int o = 16; o; o >>= 1) {
            d += __shfl_xor_sync(0xffffffffu, d, o);
            n += __shfl_xor_sync(0xffffffffu, n, o);
        }
        if (lane == 0) { sdot[row] = d; snrm[row] = n; }
    }
    __syncthreads();
    if (t < 128) {
        float c = sdot[t] / (sqrtf(snrm[0]) * sqrtf(snrm[t]));
#pragma unroll
        for (int o = 16; o; o >>= 1) c += __shfl_xor_sync(0xffffffffu, c, o);
        if (lane == 0) red[t >> 5] = c;
    }
    __syncthreads();
    if (t == 0) g_s = (red[0] + red[1] + red[2] + red[3]) * (1.0f / 128.0f);
}

// ---------------------------------------------------------------------------
// Final masked-mean gather: TWO output rows per warp.
// idxmat[r0*16 + lane] covers rows r0 (lanes 0-15) and r0+1 (lanes 16-31).
// fp16 chains x4 per row, fp32 combine. Output stores streamed (__stcs).
// ---------------------------------------------------------------------------
__global__ void k_gather16x2(const uint2* __restrict__ src,
                             const int* __restrict__ idxmat,
                             float4* __restrict__ dst, int rows) {
    int wg = (blockIdx.x * blockDim.x + threadIdx.x) >> 5;   // warp id
    int lane = threadIdx.x & 31;
    int r0 = wg * 2;
    if (r0 >= rows) return;

    int idx = idxmat[r0 * 16 + lane];          // both rows, coalesced
    unsigned on = __ballot_sync(0xffffffffu, idx > 0);
    unsigned on0 = on & 0xFFFFu, on1 = on >> 16;
    int cnt0 = __popc(on0), cnt1 = __popc(on1);
    float wnf0 = cnt0 ? (1.0f / (float)cnt0) : (1.0f / 16.0f);
    float wnf1 = cnt1 ? (1.0f / (float)cnt1) : (1.0f / 16.0f);
    if (cnt0 == 0) on0 = 0xFFFFu;
    if (cnt1 == 0) on1 = 0xFFFFu;
    __half2 wn0 = __half2half2(__float2half_rn(wnf0));
    __half2 wn1 = __half2half2(__float2half_rn(wnf1));
    const __half2 z2 = __half2half2(__ushort_as_half(0));

    __half2 a0[4][2], a1[4][2];
#pragma unroll
    for (int j = 0; j < 4; j++) {
        a0[j][0] = z2; a0[j][1] = z2;
        a1[j][0] = z2; a1[j][1] = z2;
    }

#pragma unroll
    for (int a = 0; a < 16; a++) {
        int ia0 = __shfl_sync(0xffffffffu, idx, a);
        int ia1 = __shfl_sync(0xffffffffu, idx, a + 16);
        __half2 w0 = ((on0 >> a) & 1u) ? wn0 : z2;
        __half2 w1 = ((on1 >> a) & 1u) ? wn1 : z2;
        uint2 u0 = src[ia0 * 32 + lane];
        uint2 u1 = src[ia1 * 32 + lane];
        a0[a & 3][0] = __hfma2(w0, *(__half2*)&u0.x, a0[a & 3][0]);
        a0[a & 3][1] = __hfma2(w0, *(__half2*)&u0.y, a0[a & 3][1]);
        a1[a & 3][0] = __hfma2(w1, *(__half2*)&u1.x, a1[a & 3][0]);
        a1[a & 3][1] = __hfma2(w1, *(__half2*)&u1.y, a1[a & 3][1]);
    }
    float2 p01 = __half22float2(a0[0][0]);
    float2 p23 = __half22float2(a0[0][1]);
    float2 q01 = __half22float2(a1[0][0]);
    float2 q23 = __half22float2(a1[0][1]);
#pragma unroll
    for (int j = 1; j < 4; j++) {
        float2 f;
        f = __half22float2(a0[j][0]); p01.x += f.x; p01.y += f.y;
        f = __half22float2(a0[j][1]); p23.x += f.x; p23.y += f.y;
        f = __half22float2(a1[j][0]); q01.x += f.x; q01.y += f.y;
        f = __half22float2(a1[j][1]); q23.x += f.x; q23.y += f.y;
    }
    __stcs(&dst[r0 * 32 + lane], make_float4(p01.x, p01.y, p23.x, p23.y));
    if (r0 + 1 < rows)
        __stcs(&dst[(r0 + 1) * 32 + lane],
               make_float4(q01.x, q01.y, q23.x, q23.y));
}

// ---------------------------------------------------------------------------
// Fused: gather(x_h, seq) -> sA, then e1 = relu(s*A@W1)@W2 (fp16 mma+ldsm)
// 128 rows/CTA, 512 threads (16 warps), warp tile 32x32, 2 CTAs/SM.
// ---------------------------------------------------------------------------
#define PH 136
#define SA_HALFS (128 * PH)
#define SMEM_TOTAL (3 * SA_HALFS * 2)

__device__ __forceinline__ void do_gemm_ldsm(uint32_t aA0, uint32_t aA1,
                                             uint32_t bA0, uint32_t bA1,
                                             float acc[2][4][4]) {
#pragma unroll
    for (int k0 = 0; k0 < 128; k0 += 16) {
        uint32_t a0[4], a1[4], b0[4], b1[4];
        ldsm_x4(a0, aA0 + k0 * 2);
        ldsm_x4(a1, aA1 + k0 * 2);
        ldsm_x4(b0, bA0 + k0 * 2);
        ldsm_x4(b1, bA1 + k0 * 2);
        mma16(acc[0][0], a0, b0[0], b0[2]);
        mma16(acc[0][1], a0, b0[1], b0[3]);
        mma16(acc[0][2], a0, b1[0], b1[2]);
        mma16(acc[0][3], a0, b1[1], b1[3]);
        mma16(acc[1][0], a1, b0[0], b0[2]);
        mma16(acc[1][1], a1, b0[1], b0[3]);
        mma16(acc[1][2], a1, b1[0], b1[2]);
        mma16(acc[1][3], a1, b1[1], b1[3]);
    }
}

__global__ void __launch_bounds__(512, 2)
k_fused(const uint2* __restrict__ xh, const int* __restrict__ seq,
        __half2* __restrict__ e1h, int M) {
    extern __shared__ __align__(16) __half smem[];
    __half* sA   = smem;
    __half* sW1t = smem + SA_HALFS;
    __half* sW2t = sW1t + SA_HALFS;

    int t = threadIdx.x;
    int w = t >> 5, lane = t & 31;
    int g = lane >> 2, tig = lane & 3;
    int row0 = blockIdx.x * 128;

    // ---- weight smem fills (coalesced 8B, conflict-free) ----
    for (int i = t; i < 4096; i += 512) {
        int r = i >> 5, c = i & 31;
        *(uint2*)&sW1t[r * PH + c * 4] = g_w1t[r * 32 + c];
        *(uint2*)&sW2t[r * PH + c * 4] = g_w2t[r * 32 + c];
    }

    // ---- phase 1: gather 128 edge rows into sA (one warp/row, x8) ----
    const __half2 z2 = __half2half2(__ushort_as_half(0));
#pragma unroll
    for (int it = 0; it < 8; it++) {
        int rr = it * 16 + w;                 // 0..127
        int row = row0 + rr;
        int idx = 0;
        if (row < M) idx = seq[row * 32 + lane];
        unsigned on = __ballot_sync(0xffffffffu, idx > 0);
        int cnt = __popc(on);
        float wn = cnt ? (1.0f / (float)cnt) : (1.0f / 32.0f);
        if (cnt == 0 && row < M) on = 0xFFFFFFFFu;   // tail rows stay zero
        __half2 wn2 = __half2half2(__float2half_rn(wn));

        __half2 acc[8][2];
#pragma unroll
        for (int j = 0; j < 8; j++) { acc[j][0] = z2; acc[j][1] = z2; }
#pragma unroll
        for (int a = 0; a < 32; a++) {
            int ia = __shfl_sync(0xffffffffu, idx, a);
            __half2 wa = ((on >> a) & 1u) ? wn2 : z2;
            uint2 u = xh[ia * 32 + lane];
            acc[a & 7][0] = __hfma2(wa, *(__half2*)&u.x, acc[a & 7][0]);
            acc[a & 7][1] = __hfma2(wa, *(__half2*)&u.y, acc[a & 7][1]);
        }
        float2 c01 = __half22float2(acc[0][0]);
        float2 c23 = __half22float2(acc[0][1]);
#pragma unroll
        for (int j = 1; j < 8; j++) {
            float2 f0 = __half22float2(acc[j][0]);
            float2 f1 = __half22float2(acc[j][1]);
            c01.x += f0.x; c01.y += f0.y;
            c23.x += f1.x; c23.y += f1.y;
        }
        __half2 h0 = __floats2half2_rn(c01.x, c01.y);
        __half2 h1 = __floats2half2_rn(c23.x, c23.y);
        *(uint2*)&sA[rr * PH + lane * 4] =
            make_uint2(*(uint32_t*)&h0, *(uint32_t*)&h1);
    }
    __syncthreads();

    int mrow0 = (w & 3) * 32;       // warp row strip
    int ncol0 = (w >> 2) * 32;      // warp col strip

    // ldmatrix lane addresses
    int mi = lane >> 3, ri = lane & 7;
    int rsel = (mi & 1) * 8 + ri;
    int ksel = (mi >> 1) * 8;
    uint32_t sA_s  = (uint32_t)__cvta_generic_to_shared(sA);
    uint32_t sW1_s = (uint32_t)__cvta_generic_to_shared(sW1t);
    uint32_t sW2_s = (uint32_t)__cvta_generic_to_shared(sW2t);
    uint32_t aA0 = sA_s + ((mrow0 + rsel) * PH + ksel) * 2;
    uint32_t aA1 = aA0 + 16 * PH * 2;
    uint32_t off_b = (uint32_t)(((ncol0 + rsel) * PH + ksel) * 2);
    uint32_t b1A0 = sW1_s + off_b, b1A1 = b1A0 + 16 * PH * 2;
    uint32_t b2A0 = sW2_s + off_b, b2A1 = b2A0 + 16 * PH * 2;

    float acc[2][4][4];
#pragma unroll
    for (int ms = 0; ms < 2; ms++)
#pragma unroll
        for (int ns = 0; ns < 4; ns++)
#pragma unroll
            for (int j = 0; j < 4; j++) acc[ms][ns][j] = 0.f;

    // ================= GEMM 1 =================
    do_gemm_ldsm(aA0, aA1, b1A0, b1A1, acc);

    float s_nw = g_s;
    __syncthreads();    // all warps done reading sA before overwrite

    // relu(s * acc) -> sA (fp16)
#pragma unroll
    for (int ms = 0; ms < 2; ms++) {
#pragma unroll
        for (int ns = 0; ns < 4; ns++) {
            int r0 = mrow0 + ms * 16 + g;
            int c0 = ncol0 + ns * 8 + 2 * tig;
            __half2 lo = __floats2half2_rn(fmaxf(acc[ms][ns][0] * s_nw, 0.f),
                                           fmaxf(acc[ms][ns][1] * s_nw, 0.f));
            __half2 hi = __floats2half2_rn(fmaxf(acc[ms][ns][2] * s_nw, 0.f),
                                           fmaxf(acc[ms][ns][3] * s_nw, 0.f));
            *(__half2*)&sA[r0 * PH + c0] = lo;
            *(__half2*)&sA[(r0 + 8) * PH + c0] = hi;
#pragma unroll
            for (int j = 0; j < 4; j++) acc[ms][ns][j] = 0.f;
        }
    }
    __syncthreads();

    // ================= GEMM 2 =================
    do_gemm_ldsm(aA0, aA1, b2A0, b2A1, acc);

    // write e1 (fp16)
#pragma unroll
    for (int ms = 0; ms < 2; ms++) {
#pragma unroll
        for (int ns = 0; ns < 4; ns++) {
            int r = row0 + mrow0 + ms * 16 + g;
            int c0 = ncol0 + ns * 8 + 2 * tig;
            if (r < M)
                e1h[(size_t)r * 64 + (c0 >> 1)] =
                    __floats2half2_rn(acc[ms][ns][0], acc[ms][ns][1]);
            if (r + 8 < M)
                e1h[(size_t)(r + 8) * 64 + (c0 >> 1)] =
                    __floats2half2_rn(acc[ms][ns][2], acc[ms][ns][3]);
        }
    }
}

// ---------------------------------------------------------------------------
extern "C" void kernel_launch(void* const* d_in, const int* in_sizes, int n_in,
                              void* d_out, int out_size) {
    const float* x    = (const float*)d_in[0];   // [100000,128]
    const int*   seq  = (const int*)d_in[1];     // [50000,32]
    const int*   useq = (const int*)d_in[2];     // [100000,16]
    const float* w1   = (const float*)d_in[4];   // [128,128]
    const float* w2   = (const float*)d_in[5];   // [128,128]
    const float* w3   = (const float*)d_in[6];   // [128,128]

    void *p_xh, *p_e1h;
    cudaGetSymbolAddress(&p_xh, g_xh);
    cudaGetSymbolAddress(&p_e1h, g_e1h);

    cudaFuncSetAttribute(k_fused, cudaFuncAttributeMaxDynamicSharedMemorySize,
                         SMEM_TOTAL);

    // weights transpose + inter_nw + x->fp16 (one launch, MLP=8 convert)
    k_prep<<<33 + XCONV_BLOCKS, 512>>>(w1, w2, w3, (const float4*)x);

    // gather32 + dual GEMM fused
    k_fused<<<TILES, 512, SMEM_TOTAL>>>((const uint2*)p_xh, seq,
                                        (__half2*)p_e1h, N_EDGES);

    // out[n] = masked-mean_k e1_h[useq[n,k]]  (2 rows/warp)
    k_gather16x2<<<(N_NODESC / 2 + 7) / 8, 256>>>((const uint2*)p_e1h, useq,
                                                  (float4*)d_out, N_NODESC);
}